// round 15
// baseline (speedup 1.0000x reference)
#include <cuda_runtime.h>
#include <cstdint>

// PermutationInvariantNet: B=8, N=256, IN_DIM=2, D=128, H=512, L=2
// Tokens T = B*N = 2048. fp32.
// 7 launches: embed, 2x { stats, pool, ff }.
// ff NEW: column-split warpgroups. kg0 computes Us cols 0..63 fully
// (relu+bias at store, no partial combine), kg1 cols 64..127; ff2 contracts
// each kg's own Us half (k-split for free), acc2 combined once at the end.
// pool: R13/R14 concurrent-halves version (proven).

#define T_TOK 2048
#define NB 8
#define NN 256
#define DD 128
#define HH 512
#define LN_EPS 1e-5f
#define NEG_INF -3.402823466e38f

__device__ __align__(16) float g_h[T_TOK * DD];   // hidden state (1 MB)
__device__ float g_m1[NB * DD];                   // per-batch per-feature max
__device__ float g_m2[NB * DD];                   // second max
__device__ int   g_i1[NB * DD];                   // argmax (n within batch)

// -------- cp.async helpers --------
__device__ __forceinline__ void cp_async16(uint32_t dst, const void* src) {
    asm volatile("cp.async.cg.shared.global [%0], [%1], 16;" :: "r"(dst), "l"(src));
}
__device__ __forceinline__ void cp_commit() { asm volatile("cp.async.commit_group;"); }
__device__ __forceinline__ void cp_wait1()  { asm volatile("cp.async.wait_group 1;"); }
__device__ __forceinline__ void cp_wait0()  { asm volatile("cp.async.wait_group 0;"); }
__device__ __forceinline__ void bar_sync(int id, int cnt) {
    asm volatile("bar.sync %0, %1;" :: "r"(id), "r"(cnt) : "memory");
}

// ===================== embed + LN =====================
__global__ void __launch_bounds__(128)
embed_ln_kernel(const float* __restrict__ x, const float* __restrict__ We,
                const float* __restrict__ be, const float* __restrict__ ge,
                const float* __restrict__ bge) {
    __shared__ float sh[8];
    int t = blockIdx.x, d = threadIdx.x;
    float x0 = x[t * 2 + 0];
    float x1 = x[t * 2 + 1];
    float y = fmaf(x0, We[d], fmaf(x1, We[DD + d], be[d]));
    float s = y, q = y * y;
#pragma unroll
    for (int o = 16; o > 0; o >>= 1) {
        s += __shfl_xor_sync(0xffffffffu, s, o);
        q += __shfl_xor_sync(0xffffffffu, q, o);
    }
    int lane = threadIdx.x & 31, w = threadIdx.x >> 5;
    if (lane == 0) { sh[w] = s; sh[4 + w] = q; }
    __syncthreads();
    s = sh[0] + sh[1] + sh[2] + sh[3];
    q = sh[4] + sh[5] + sh[6] + sh[7];
    float mean = s * (1.0f / DD);
    float rstd = rsqrtf(q * (1.0f / DD) - mean * mean + LN_EPS);
    g_h[t * DD + d] = (y - mean) * rstd * ge[d] + bge[d];
}

// ===================== per-batch (max1, max2, argmax) over N=256 ==========
__global__ void __launch_bounds__(512)
stats_kernel() {
    int b = blockIdx.x;
    int d = threadIdx.x;
    int s = threadIdx.y;
    const float* hb = g_h + b * NN * DD;

    float m1 = NEG_INF, m2 = NEG_INF;
    int i1 = 0;
    int n0 = s * (NN / 4);
#pragma unroll 8
    for (int n = n0; n < n0 + NN / 4; n++) {
        float v = hb[n * DD + d];
        if (v > m1) { m2 = m1; m1 = v; i1 = n; }
        else if (v > m2) { m2 = v; }
    }
    __shared__ float sm1[4][DD], sm2[4][DD];
    __shared__ int si1[4][DD];
    sm1[s][d] = m1; sm2[s][d] = m2; si1[s][d] = i1;
    __syncthreads();
    if (s == 0) {
#pragma unroll
        for (int j = 1; j < 4; j++) {
            float a1 = sm1[j][d], a2 = sm2[j][d];
            int ai = si1[j][d];
            if (a1 > m1) { m2 = fmaxf(m1, a2); m1 = a1; i1 = ai; }
            else         { m2 = fmaxf(m2, a1); }
        }
        g_m1[b * DD + d] = m1;
        g_m2[b * DD + d] = m2;
        g_i1[b * DD + d] = i1;
    }
}

// ===================== pool (R13/R14, proven): concurrent kgroup halves ====
// h' = LN(h + [h, loo(h)] @ Wp + bp); in-place on g_h.
// smem floats: As 0 [16][256]=4096 | Ws 4096 [256][128]=32768
//              | part 36864 [16][128]=2048 | lnS 38912 [2][16] | lnQ 38944
#define POOL_SMEM (38976 * 4)
__global__ void __launch_bounds__(512, 1)
pool_kernel(const float* __restrict__ Wp, const float* __restrict__ bp,
            const float* __restrict__ gp, const float* __restrict__ bgp) {
    extern __shared__ float sm[];
    float (*As)[256]   = reinterpret_cast<float (*)[256]>(sm);
    float (*Ws)[DD]    = reinterpret_cast<float (*)[DD]>(sm + 4096);
    float (*part)[DD]  = reinterpret_cast<float (*)[DD]>(sm + 36864);
    float (*lnS)[16]   = reinterpret_cast<float (*)[16]>(sm + 38912);
    float (*lnQ)[16]   = reinterpret_cast<float (*)[16]>(sm + 38944);

    const int tid = threadIdx.x;
    const int kg = tid >> 8;            // 0 or 1 (whole warps)
    const int t8 = tid & 255;
    const int lane = t8 & 31, wid8 = t8 >> 5;
    const int rg = wid8 & 3, cg = wid8 >> 2;
    const int rg4 = rg * 4;
    const int c2 = cg * 64 + lane * 2;
    const int row0 = blockIdx.x * 16;
    const int b = row0 >> 8;
    const int nbase = row0 & 255;

    uint32_t ws_base = (uint32_t)__cvta_generic_to_shared(&Ws[0][0]);

    float acc[4][2];
#pragma unroll
    for (int r = 0; r < 4; r++) { acc[r][0] = 0.f; acc[r][1] = 0.f; }

    if (kg == 0) {
#pragma unroll
        for (int i = 0; i < 16; i++) {
            int t16 = t8 + i * 256;
            int k = t16 >> 5, c4 = (t16 & 31) << 2;
            cp_async16(ws_base + (uint32_t)(k * DD + c4) * 4, Wp + k * DD + c4);
        }
        cp_commit();
#pragma unroll
        for (int i = 0; i < 2; i++) {
            int idx4 = (t8 + i * 256) * 4;
            int r = idx4 >> 7, k = idx4 & 127;
            *reinterpret_cast<float4*>(&As[r][k]) =
                *reinterpret_cast<const float4*>(&g_h[row0 * DD + idx4]);
        }
        cp_wait0();
        bar_sync(1, 256);
#pragma unroll 4
        for (int k0 = 0; k0 < 128; k0 += 4) {
            float a[4][4];
#pragma unroll
            for (int r = 0; r < 4; r++)
                *reinterpret_cast<float4*>(a[r]) =
                    *reinterpret_cast<const float4*>(&As[rg4 + r][k0]);
#pragma unroll
            for (int kk = 0; kk < 4; kk++) {
                float2 w = *reinterpret_cast<const float2*>(&Ws[k0 + kk][c2]);
#pragma unroll
                for (int r = 0; r < 4; r++) {
                    acc[r][0] = fmaf(a[r][kk], w.x, acc[r][0]);
                    acc[r][1] = fmaf(a[r][kk], w.y, acc[r][1]);
                }
            }
        }
    } else {
        const float* Wbot = Wp + DD * DD;
#pragma unroll
        for (int i = 0; i < 16; i++) {
            int t16 = t8 + i * 256;
            int k = t16 >> 5, c4 = (t16 & 31) << 2;
            cp_async16(ws_base + (uint32_t)((128 + k) * DD + c4) * 4,
                       Wbot + k * DD + c4);
        }
        cp_commit();
#pragma unroll
        for (int i = 0; i < 8; i++) {
            int idx = t8 + i * 256;
            int r = idx >> 7, k = idx & 127;
            int am = g_i1[b * DD + k];
            float m1 = g_m1[b * DD + k], m2 = g_m2[b * DD + k];
            As[r][128 + k] = (nbase + r == am) ? m2 : m1;
        }
        cp_wait0();
        bar_sync(2, 256);
#pragma unroll 4
        for (int k0 = 128; k0 < 256; k0 += 4) {
            float a[4][4];
#pragma unroll
            for (int r = 0; r < 4; r++)
                *reinterpret_cast<float4*>(a[r]) =
                    *reinterpret_cast<const float4*>(&As[rg4 + r][k0]);
#pragma unroll
            for (int kk = 0; kk < 4; kk++) {
                float2 w = *reinterpret_cast<const float2*>(&Ws[k0 + kk][c2]);
#pragma unroll
                for (int r = 0; r < 4; r++) {
                    acc[r][0] = fmaf(a[r][kk], w.x, acc[r][0]);
                    acc[r][1] = fmaf(a[r][kk], w.y, acc[r][1]);
                }
            }
        }
#pragma unroll
        for (int r = 0; r < 4; r++) {
            part[rg4 + r][c2] = acc[r][0];
            part[rg4 + r][c2 + 1] = acc[r][1];
        }
    }
    __syncthreads();

    if (kg == 0) {
        float v[4][2], s[4], q[4];
        float bp0 = bp[c2], bp1 = bp[c2 + 1];
#pragma unroll
        for (int r = 0; r < 4; r++) {
            v[r][0] = acc[r][0] + part[rg4 + r][c2] + bp0 + As[rg4 + r][c2];
            v[r][1] = acc[r][1] + part[rg4 + r][c2 + 1] + bp1 + As[rg4 + r][c2 + 1];
            s[r] = v[r][0] + v[r][1];
            q[r] = v[r][0] * v[r][0] + v[r][1] * v[r][1];
        }
#pragma unroll
        for (int o = 16; o > 0; o >>= 1)
#pragma unroll
            for (int r = 0; r < 4; r++) {
                s[r] += __shfl_xor_sync(0xffffffffu, s[r], o);
                q[r] += __shfl_xor_sync(0xffffffffu, q[r], o);
            }
        if (lane == 0)
#pragma unroll
            for (int r = 0; r < 4; r++) { lnS[cg][rg4 + r] = s[r]; lnQ[cg][rg4 + r] = q[r]; }
        bar_sync(1, 256);
        float g0 = gp[c2], g1 = gp[c2 + 1], e0 = bgp[c2], e1 = bgp[c2 + 1];
#pragma unroll
        for (int r = 0; r < 4; r++) {
            float S = lnS[0][rg4 + r] + lnS[1][rg4 + r];
            float Q = lnQ[0][rg4 + r] + lnQ[1][rg4 + r];
            float mean = S * (1.0f / DD);
            float rstd = rsqrtf(Q * (1.0f / DD) - mean * mean + LN_EPS);
            float2 o;
            o.x = (v[r][0] - mean) * rstd * g0 + e0;
            o.y = (v[r][1] - mean) * rstd * g1 + e1;
            *reinterpret_cast<float2*>(&g_h[(row0 + rg4 + r) * DD + c2]) = o;
        }
    }
}

// ===================== fused FF (column-split kgroups) =====================
// h' = LN(h + relu(h@W1+b1)@W2 + b2). 4 H-chunks of 128, W1 double-buffered.
// 256 thr = 8 warps; kg = wid>>2 owns Us cols [kg*64, kg*64+64).
// ff1 (per kg): 4 warps = 2rg x 2cg, thread = 8 rows x 1 col, FULL 128-k
//   contraction -> complete Us values, relu+bias at store (no combine pass).
// ff2 (per kg): 4 warps = 2rg x 2cg, thread = 8 rows x 2 cols, contracts
//   k in [kg*64, kg*64+64) = its own Us half (kg-local barrier only).
// acc2 partials combined once at the end through the dead Us buffer.
// smem floats: hs 0 [16][128] | W1c 2048 [2][128][128] | W2c 34816 [128][128]
//              | Us 51200 [16][128] | lnS 53248 [2][16] | lnQ 53280
#define FF_SMEM (53312 * 4)
template <bool FINAL>
__global__ void __launch_bounds__(256, 1)
ff_fused_kernel(const float* __restrict__ W1, const float* __restrict__ b1,
                const float* __restrict__ W2, const float* __restrict__ b2,
                const float* __restrict__ gf, const float* __restrict__ bgf,
                float* __restrict__ out) {
    extern __shared__ float sm[];
    float (*hs)[DD]  = reinterpret_cast<float (*)[DD]>(sm);
    float* W1c       = sm + 2048;
    float (*W2c)[DD] = reinterpret_cast<float (*)[DD]>(sm + 34816);
    float (*Us)[DD]  = reinterpret_cast<float (*)[DD]>(sm + 51200);
    float (*lnS)[16] = reinterpret_cast<float (*)[16]>(sm + 53248);
    float (*lnQ)[16] = reinterpret_cast<float (*)[16]>(sm + 53280);

    const int tid = threadIdx.x;
    const int lane = tid & 31, wid = tid >> 5;
    const int kg = wid >> 2;            // warps 0-3 kg0, 4-7 kg1
    const int w4 = wid & 3;
    const int rg = w4 & 1;              // 2 rowgroups of 8 rows
    const int cg = w4 >> 1;             // 2 colgroups
    const int rg8 = rg * 8;
    const int kcol = kg * 64 + cg * 32 + lane;  // ff1 output col (cpt=1)
    const int c2 = cg * 64 + lane * 2;          // ff2 output cols (cpt=2)
    const int kb = kg * 64;             // ff2 k-offset (own Us half)
    const int row0 = blockIdx.x * 16;

    const uint32_t w1s = (uint32_t)__cvta_generic_to_shared(W1c);
    const uint32_t w2s = (uint32_t)__cvta_generic_to_shared(&W2c[0][0]);

    // chunk-0 weight loads (256 threads, 16 float4 each per buffer)
#pragma unroll
    for (int i = 0; i < 16; i++) {
        int t16 = tid + i * 256;
        int k = t16 >> 5, c4 = (t16 & 31) << 2;
        cp_async16(w1s + (uint32_t)(k * DD + c4) * 4, W1 + k * HH + c4);
    }
    cp_commit();
#pragma unroll
    for (int i = 0; i < 16; i++) {
        int t16 = tid + i * 256;
        int k = t16 >> 5, c4 = (t16 & 31) << 2;
        cp_async16(w2s + (uint32_t)(k * DD + c4) * 4, W2 + k * DD + c4);
    }
    cp_commit();

    // load h rows (doubles as residual): 2 float4 per thread
#pragma unroll
    for (int i = 0; i < 2; i++) {
        int idx4 = (tid + i * 256) * 4;
        *reinterpret_cast<float4*>(&hs[idx4 >> 7][idx4 & 127]) =
            *reinterpret_cast<const float4*>(&g_h[row0 * DD + idx4]);
    }

    float acc2[8][2];
#pragma unroll
    for (int r = 0; r < 8; r++) { acc2[r][0] = 0.f; acc2[r][1] = 0.f; }

    for (int ci = 0; ci < 4; ci++) {
        const int c0 = ci * 128;
        const float* W1b = W1c + (ci & 1) * 16384;

        cp_wait1();          // W1(ci) landed (W2(ci) may still fly)
        __syncthreads();     // cp.async visibility + hs/Us/W1-buf hazards

        // ---- ff1: full 128-k contraction, thread = 8 rows x 1 col ----
        float acc1[8];
#pragma unroll
        for (int r = 0; r < 8; r++) acc1[r] = 0.f;
#pragma unroll 4
        for (int k0 = 0; k0 < DD; k0 += 4) {
            float a[8][4];
#pragma unroll
            for (int r = 0; r < 8; r++)
                *reinterpret_cast<float4*>(a[r]) =
                    *reinterpret_cast<const float4*>(&hs[rg8 + r][k0]);
#pragma unroll
            for (int kk = 0; kk < 4; kk++) {
                float w = W1b[(k0 + kk) * DD + kcol];
#pragma unroll
                for (int r = 0; r < 8; r++)
                    acc1[r] = fmaf(a[r][kk], w, acc1[r]);
            }
        }
        // Us (this kg's half) = relu(acc1 + b1) — complete values, no combine
        {
            float bb = b1[c0 + kcol];
#pragma unroll
            for (int r = 0; r < 8; r++)
                Us[rg8 + r][kcol] = fmaxf(acc1[r] + bb, 0.0f);
        }

        // prefetch W1(ci+1) into the other buffer (overlaps ff2)
        if (ci < 3) {
            uint32_t dst = w1s + (uint32_t)(((ci + 1) & 1) * 16384) * 4;
            const float* src = W1 + c0 + 128;
#pragma unroll
            for (int i = 0; i < 16; i++) {
                int t16 = tid + i * 256;
                int k = t16 >> 5, c4 = (t16 & 31) << 2;
                cp_async16(dst + (uint32_t)(k * DD + c4) * 4, src + k * HH + c4);
            }
            cp_commit();
        }

        if (ci < 3) cp_wait1(); else cp_wait0();   // W2(ci) landed
        bar_sync(1 + kg, 128);   // kg-local: own Us half visible to own kg
        __syncthreads();          // block-wide: W2 cp.async data visible

        // ---- ff2: acc2 += Us[:, kb..kb+64) @ W2c[kb..kb+64, :] ----
#pragma unroll 4
        for (int k0 = kb; k0 < kb + 64; k0 += 4) {
            float a[8][4];
#pragma unroll
            for (int r = 0; r < 8; r++)
                *reinterpret_cast<float4*>(a[r]) =
                    *reinterpret_cast<const float4*>(&Us[rg8 + r][k0]);
#pragma unroll
            for (int kk = 0; kk < 4; kk++) {
                float2 w = *reinterpret_cast<const float2*>(&W2c[k0 + kk][c2]);
#pragma unroll
                for (int r = 0; r < 8; r++) {
                    acc2[r][0] = fmaf(a[r][kk], w.x, acc2[r][0]);
                    acc2[r][1] = fmaf(a[r][kk], w.y, acc2[r][1]);
                }
            }
        }
        __syncthreads();    // W2c + Us fully consumed before next prefetch/write

        // prefetch W2(ci+1) (overlaps next ff1)
        if (ci < 3) {
            const float* src = W2 + (c0 + 128) * DD;
#pragma unroll
            for (int i = 0; i < 16; i++) {
                int t16 = tid + i * 256;
                int k = t16 >> 5, c4 = (t16 & 31) << 2;
                cp_async16(w2s + (uint32_t)(k * DD + c4) * 4, src + k * DD + c4);
            }
            cp_commit();
        }
    }

    // ---- epilogue: combine kg partials through dead Us, +b2 +res, LN ----
    if (kg == 1) {
#pragma unroll
        for (int r = 0; r < 8; r++) {
            float2 u;
            u.x = acc2[r][0];
            u.y = acc2[r][1];
            *reinterpret_cast<float2*>(&Us[rg8 + r][c2]) = u;
        }
    }
    __syncthreads();

    if (kg == 0) {
        float v[8][2], s[8], q[8];
        float b20 = b2[c2], b21 = b2[c2 + 1];
#pragma unroll
        for (int r = 0; r < 8; r++) {
            v[r][0] = acc2[r][0] + Us[rg8 + r][c2] + b20 + hs[rg8 + r][c2];
            v[r][1] = acc2[r][1] + Us[rg8 + r][c2 + 1] + b21 + hs[rg8 + r][c2 + 1];
            s[r] = v[r][0] + v[r][1];
            q[r] = v[r][0] * v[r][0] + v[r][1] * v[r][1];
        }
#pragma unroll
        for (int o = 16; o > 0; o >>= 1)
#pragma unroll
            for (int r = 0; r < 8; r++) {
                s[r] += __shfl_xor_sync(0xffffffffu, s[r], o);
                q[r] += __shfl_xor_sync(0xffffffffu, q[r], o);
            }
        if (lane == 0)
#pragma unroll
            for (int r = 0; r < 8; r++) { lnS[cg][rg8 + r] = s[r]; lnQ[cg][rg8 + r] = q[r]; }
        bar_sync(1, 128);     // kg0's 4 warps
        float g0 = gf[c2], g1 = gf[c2 + 1], e0 = bgf[c2], e1 = bgf[c2 + 1];
#pragma unroll
        for (int r = 0; r < 8; r++) {
            float S = lnS[0][rg8 + r] + lnS[1][rg8 + r];
            float Q = lnQ[0][rg8 + r] + lnQ[1][rg8 + r];
            float mean = S * (1.0f / DD);
            float rstd = rsqrtf(Q * (1.0f / DD) - mean * mean + LN_EPS);
            float2 o;
            o.x = (v[r][0] - mean) * rstd * g0 + e0;
            o.y = (v[r][1] - mean) * rstd * g1 + e1;
            int row = row0 + rg8 + r;
            if (FINAL) *reinterpret_cast<float2*>(&out[row * DD + c2]) = o;
            else       *reinterpret_cast<float2*>(&g_h[row * DD + c2]) = o;
        }
    }
}

extern "C" void kernel_launch(void* const* d_in, const int* in_sizes, int n_in,
                              void* d_out, int out_size) {
    const float* x   = (const float*)d_in[0];   // (8,256,2)
    const float* We  = (const float*)d_in[1];   // (2,128)
    const float* be  = (const float*)d_in[2];
    const float* ge  = (const float*)d_in[3];
    const float* bge = (const float*)d_in[4];
    const float* Wp  = (const float*)d_in[5];   // (2,256,128)
    const float* bp  = (const float*)d_in[6];
    const float* gp  = (const float*)d_in[7];
    const float* bgp = (const float*)d_in[8];
    const float* W1  = (const float*)d_in[9];   // (2,128,512)
    const float* b1  = (const float*)d_in[10];
    const float* W2  = (const float*)d_in[11];  // (2,512,128)
    const float* b2  = (const float*)d_in[12];
    const float* gf  = (const float*)d_in[13];
    const float* bgf = (const float*)d_in[14];
    float* out = (float*)d_out;                 // (8,256,128) fp32

    cudaFuncSetAttribute(pool_kernel,
                         cudaFuncAttributeMaxDynamicSharedMemorySize, POOL_SMEM);
    cudaFuncSetAttribute(ff_fused_kernel<false>,
                         cudaFuncAttributeMaxDynamicSharedMemorySize, FF_SMEM);
    cudaFuncSetAttribute(ff_fused_kernel<true>,
                         cudaFuncAttributeMaxDynamicSharedMemorySize, FF_SMEM);

    embed_ln_kernel<<<T_TOK, 128>>>(x, We, be, ge, bge);

    for (int i = 0; i < 2; i++) {
        stats_kernel<<<NB, dim3(128, 4)>>>();

        pool_kernel<<<T_TOK / 16, 512, POOL_SMEM>>>(
            Wp + i * 2 * DD * DD, bp + i * DD, gp + i * DD, bgp + i * DD);

        if (i == 1)
            ff_fused_kernel<true><<<T_TOK / 16, 256, FF_SMEM>>>(
                W1 + i * DD * HH, b1 + i * HH, W2 + i * HH * DD, b2 + i * DD,
                gf + i * DD, bgf + i * DD, out);
        else
            ff_fused_kernel<false><<<T_TOK / 16, 256, FF_SMEM>>>(
                W1 + i * DD * HH, b1 + i * HH, W2 + i * HH * DD, b2 + i * DD,
                gf + i * DD, bgf + i * DD, nullptr);
    }
}

// round 16
// speedup vs baseline: 1.0913x; 1.0913x over previous
#include <cuda_runtime.h>
#include <cstdint>

// PermutationInvariantNet: B=8, N=256, IN_DIM=2, D=128, H=512, L=2
// Tokens T = B*N = 2048. fp32.
// 7 launches: embed, 2x { stats(64 blocks), pool(merge+gemm+LN), ff }.
// ff: R14-proven rpt=8 k-split core (at ~85% of its FFMA-pipe floor).
// stats: distributed 8x8 slices; merge folded into pool kg1 prologue
// (overlaps Wb cp.async). embed: warp-per-token.

#define T_TOK 2048
#define NB 8
#define NN 256
#define DD 128
#define HH 512
#define LN_EPS 1e-5f
#define NEG_INF -3.402823466e38f

__device__ __align__(16) float g_h[T_TOK * DD];   // hidden state (1 MB)
__device__ float g_sm1[NB * 8 * DD];              // slice max1   (8 slices)
__device__ float g_sm2[NB * 8 * DD];              // slice max2
__device__ int   g_si1[NB * 8 * DD];              // slice argmax (n within batch)

// -------- cp.async helpers --------
__device__ __forceinline__ void cp_async16(uint32_t dst, const void* src) {
    asm volatile("cp.async.cg.shared.global [%0], [%1], 16;" :: "r"(dst), "l"(src));
}
__device__ __forceinline__ void cp_commit() { asm volatile("cp.async.commit_group;"); }
__device__ __forceinline__ void cp_wait1()  { asm volatile("cp.async.wait_group 1;"); }
__device__ __forceinline__ void cp_wait0()  { asm volatile("cp.async.wait_group 0;"); }
__device__ __forceinline__ void bar_sync(int id, int cnt) {
    asm volatile("bar.sync %0, %1;" :: "r"(id), "r"(cnt) : "memory");
}

// ===================== embed + LN (warp per token) =====================
// grid 128, block 512 = 16 warps; warp owns one token, lane owns d=lane+32j.
__global__ void __launch_bounds__(512)
embed_ln_kernel(const float* __restrict__ x, const float* __restrict__ We,
                const float* __restrict__ be, const float* __restrict__ ge,
                const float* __restrict__ bge) {
    int wid = threadIdx.x >> 5, lane = threadIdx.x & 31;
    int t = blockIdx.x * 16 + wid;
    float2 xx = *reinterpret_cast<const float2*>(x + t * 2);
    float y[4], s = 0.0f, q = 0.0f;
#pragma unroll
    for (int j = 0; j < 4; j++) {
        int d = lane + j * 32;
        y[j] = fmaf(xx.x, We[d], fmaf(xx.y, We[DD + d], be[d]));
        s += y[j];
        q += y[j] * y[j];
    }
#pragma unroll
    for (int o = 16; o > 0; o >>= 1) {
        s += __shfl_xor_sync(0xffffffffu, s, o);
        q += __shfl_xor_sync(0xffffffffu, q, o);
    }
    float mean = s * (1.0f / DD);
    float rstd = rsqrtf(q * (1.0f / DD) - mean * mean + LN_EPS);
#pragma unroll
    for (int j = 0; j < 4; j++) {
        int d = lane + j * 32;
        g_h[t * DD + d] = (y[j] - mean) * rstd * ge[d] + bge[d];
    }
}

// ===================== distributed stats: 64 blocks of (batch, slice) ======
// block = (b*8 + sl); 128 threads, each d scans 32 tokens -> slice partials.
__global__ void __launch_bounds__(128)
stats_kernel() {
    int blk = blockIdx.x;
    int b = blk >> 3, sl = blk & 7;
    int d = threadIdx.x;
    const float* hb = g_h + b * NN * DD;

    float m1 = NEG_INF, m2 = NEG_INF;
    int i1 = 0;
    int n0 = sl * 32;
#pragma unroll 8
    for (int n = n0; n < n0 + 32; n++) {
        float v = hb[n * DD + d];
        if (v > m1) { m2 = m1; m1 = v; i1 = n; }
        else if (v > m2) { m2 = v; }
    }
    int idx = (b * 8 + sl) * DD + d;
    g_sm1[idx] = m1;
    g_sm2[idx] = m2;
    g_si1[idx] = i1;
}

// ===================== pool: merge + gemm + res + LN (R13/R14 core) ========
// h' = LN(h + [h, loo(h)] @ Wp + bp); in-place on g_h.
// 512 thr = 2 kgroups. kg0: Wt + As-h + GEMM k 0..127.
// kg1: Wb cp.async, merge 8 slice-stats -> smem, synth pooled As, GEMM k 128..255.
// smem floats: As 0 [16][256]=4096 | Ws 4096 [256][128]=32768
//   | part 36864 [16][128]=2048 | lnS 38912 [2][16] | lnQ 38944
//   | m1f 38976 [128] | m2f 39104 [128] | i1f 39232 [128] (int)
#define POOL_SMEM (39360 * 4)
__global__ void __launch_bounds__(512, 1)
pool_kernel(const float* __restrict__ Wp, const float* __restrict__ bp,
            const float* __restrict__ gp, const float* __restrict__ bgp) {
    extern __shared__ float sm[];
    float (*As)[256]   = reinterpret_cast<float (*)[256]>(sm);
    float (*Ws)[DD]    = reinterpret_cast<float (*)[DD]>(sm + 4096);
    float (*part)[DD]  = reinterpret_cast<float (*)[DD]>(sm + 36864);
    float (*lnS)[16]   = reinterpret_cast<float (*)[16]>(sm + 38912);
    float (*lnQ)[16]   = reinterpret_cast<float (*)[16]>(sm + 38944);
    float* m1f         = sm + 38976;
    float* m2f         = sm + 39104;
    int*   i1f         = reinterpret_cast<int*>(sm + 39232);

    const int tid = threadIdx.x;
    const int kg = tid >> 8;            // 0 or 1 (whole warps)
    const int t8 = tid & 255;
    const int lane = t8 & 31, wid8 = t8 >> 5;
    const int rg = wid8 & 3, cg = wid8 >> 2;
    const int rg4 = rg * 4;
    const int c2 = cg * 64 + lane * 2;
    const int row0 = blockIdx.x * 16;
    const int b = row0 >> 8;
    const int nbase = row0 & 255;

    uint32_t ws_base = (uint32_t)__cvta_generic_to_shared(&Ws[0][0]);

    float acc[4][2];
#pragma unroll
    for (int r = 0; r < 4; r++) { acc[r][0] = 0.f; acc[r][1] = 0.f; }

    if (kg == 0) {
#pragma unroll
        for (int i = 0; i < 16; i++) {
            int t16 = t8 + i * 256;
            int k = t16 >> 5, c4 = (t16 & 31) << 2;
            cp_async16(ws_base + (uint32_t)(k * DD + c4) * 4, Wp + k * DD + c4);
        }
        cp_commit();
#pragma unroll
        for (int i = 0; i < 2; i++) {
            int idx4 = (t8 + i * 256) * 4;
            int r = idx4 >> 7, k = idx4 & 127;
            *reinterpret_cast<float4*>(&As[r][k]) =
                *reinterpret_cast<const float4*>(&g_h[row0 * DD + idx4]);
        }
        cp_wait0();
        bar_sync(1, 256);
#pragma unroll 4
        for (int k0 = 0; k0 < 128; k0 += 4) {
            float a[4][4];
#pragma unroll
            for (int r = 0; r < 4; r++)
                *reinterpret_cast<float4*>(a[r]) =
                    *reinterpret_cast<const float4*>(&As[rg4 + r][k0]);
#pragma unroll
            for (int kk = 0; kk < 4; kk++) {
                float2 w = *reinterpret_cast<const float2*>(&Ws[k0 + kk][c2]);
#pragma unroll
                for (int r = 0; r < 4; r++) {
                    acc[r][0] = fmaf(a[r][kk], w.x, acc[r][0]);
                    acc[r][1] = fmaf(a[r][kk], w.y, acc[r][1]);
                }
            }
        }
    } else {
        const float* Wbot = Wp + DD * DD;
#pragma unroll
        for (int i = 0; i < 16; i++) {
            int t16 = t8 + i * 256;
            int k = t16 >> 5, c4 = (t16 & 31) << 2;
            cp_async16(ws_base + (uint32_t)((128 + k) * DD + c4) * 4,
                       Wbot + k * DD + c4);
        }
        cp_commit();
        // merge 8 slice-stats for this batch (threads 0..127, ascending slice
        // order -> first-argmax tie semantics preserved); overlaps cp.async
        if (t8 < DD) {
            int base = b * 8 * DD + t8;
            float m1 = g_sm1[base], m2 = g_sm2[base];
            int i1 = g_si1[base];
#pragma unroll
            for (int j = 1; j < 8; j++) {
                float a1 = g_sm1[base + j * DD], a2 = g_sm2[base + j * DD];
                int ai = g_si1[base + j * DD];
                if (a1 > m1) { m2 = fmaxf(m1, a2); m1 = a1; i1 = ai; }
                else         { m2 = fmaxf(m2, a1); }
            }
            m1f[t8] = m1; m2f[t8] = m2; i1f[t8] = i1;
        }
        bar_sync(2, 256);   // merged stats visible within kg1
        // synth pooled As (cols 128..255) from smem stats
#pragma unroll
        for (int i = 0; i < 8; i++) {
            int idx = t8 + i * 256;
            int r = idx >> 7, k = idx & 127;
            As[r][128 + k] = (nbase + r == i1f[k]) ? m2f[k] : m1f[k];
        }
        cp_wait0();
        bar_sync(2, 256);
#pragma unroll 4
        for (int k0 = 128; k0 < 256; k0 += 4) {
            float a[4][4];
#pragma unroll
            for (int r = 0; r < 4; r++)
                *reinterpret_cast<float4*>(a[r]) =
                    *reinterpret_cast<const float4*>(&As[rg4 + r][k0]);
#pragma unroll
            for (int kk = 0; kk < 4; kk++) {
                float2 w = *reinterpret_cast<const float2*>(&Ws[k0 + kk][c2]);
#pragma unroll
                for (int r = 0; r < 4; r++) {
                    acc[r][0] = fmaf(a[r][kk], w.x, acc[r][0]);
                    acc[r][1] = fmaf(a[r][kk], w.y, acc[r][1]);
                }
            }
        }
#pragma unroll
        for (int r = 0; r < 4; r++) {
            part[rg4 + r][c2] = acc[r][0];
            part[rg4 + r][c2 + 1] = acc[r][1];
        }
    }
    __syncthreads();

    if (kg == 0) {
        float v[4][2], s[4], q[4];
        float bp0 = bp[c2], bp1 = bp[c2 + 1];
#pragma unroll
        for (int r = 0; r < 4; r++) {
            v[r][0] = acc[r][0] + part[rg4 + r][c2] + bp0 + As[rg4 + r][c2];
            v[r][1] = acc[r][1] + part[rg4 + r][c2 + 1] + bp1 + As[rg4 + r][c2 + 1];
            s[r] = v[r][0] + v[r][1];
            q[r] = v[r][0] * v[r][0] + v[r][1] * v[r][1];
        }
#pragma unroll
        for (int o = 16; o > 0; o >>= 1)
#pragma unroll
            for (int r = 0; r < 4; r++) {
                s[r] += __shfl_xor_sync(0xffffffffu, s[r], o);
                q[r] += __shfl_xor_sync(0xffffffffu, q[r], o);
            }
        if (lane == 0)
#pragma unroll
            for (int r = 0; r < 4; r++) { lnS[cg][rg4 + r] = s[r]; lnQ[cg][rg4 + r] = q[r]; }
        bar_sync(1, 256);
        float g0 = gp[c2], g1 = gp[c2 + 1], e0 = bgp[c2], e1 = bgp[c2 + 1];
#pragma unroll
        for (int r = 0; r < 4; r++) {
            float S = lnS[0][rg4 + r] + lnS[1][rg4 + r];
            float Q = lnQ[0][rg4 + r] + lnQ[1][rg4 + r];
            float mean = S * (1.0f / DD);
            float rstd = rsqrtf(Q * (1.0f / DD) - mean * mean + LN_EPS);
            float2 o;
            o.x = (v[r][0] - mean) * rstd * g0 + e0;
            o.y = (v[r][1] - mean) * rstd * g1 + e1;
            *reinterpret_cast<float2*>(&g_h[(row0 + rg4 + r) * DD + c2]) = o;
        }
    }
}

// ===================== fused FF (R14-proven rpt=8 k-split core) ============
// h' = LN(h + relu(h@W1+b1)@W2 + b2). 4 H-chunks of 128, W1 double-buffered.
// 256 thr = 8 warps = 2rg x 2cg x 2kg; thread = 8 rows x 2 cols, k split
// across kgs; ff1 partials combined elementwise, acc2 combined in epilogue.
// smem floats: hs 0 [16][128] | W1c 2048 [2][128][128] | W2c 34816 [128][128]
//              | Usp0 51200 [16][128] | Usp1 53248 [16][128]
//              | lnS 55296 [2][16] | lnQ 55328 [2][16]
#define FF_SMEM (55360 * 4)
template <bool FINAL>
__global__ void __launch_bounds__(256, 1)
ff_fused_kernel(const float* __restrict__ W1, const float* __restrict__ b1,
                const float* __restrict__ W2, const float* __restrict__ b2,
                const float* __restrict__ gf, const float* __restrict__ bgf,
                float* __restrict__ out) {
    extern __shared__ float sm[];
    float (*hs)[DD]   = reinterpret_cast<float (*)[DD]>(sm);
    float* W1c        = sm + 2048;
    float (*W2c)[DD]  = reinterpret_cast<float (*)[DD]>(sm + 34816);
    float (*Us)[DD]   = reinterpret_cast<float (*)[DD]>(sm + 51200);   // Usp0
    float (*Usp1)[DD] = reinterpret_cast<float (*)[DD]>(sm + 53248);
    float (*lnS)[16]  = reinterpret_cast<float (*)[16]>(sm + 55296);
    float (*lnQ)[16]  = reinterpret_cast<float (*)[16]>(sm + 55328);

    const int tid = threadIdx.x;
    const int lane = tid & 31, wid = tid >> 5;
    const int kg = wid >> 2;            // warps 0-3 kg0, 4-7 kg1
    const int rg = (wid >> 1) & 1;
    const int cg = wid & 1;
    const int rg8 = rg * 8;
    const int c2 = cg * 64 + lane * 2;
    const int kb = kg * 64;             // k-offset within each 128 range
    const int row0 = blockIdx.x * 16;

    const uint32_t w1s = (uint32_t)__cvta_generic_to_shared(W1c);
    const uint32_t w2s = (uint32_t)__cvta_generic_to_shared(&W2c[0][0]);

    // chunk-0 weight loads (256 threads, 16 float4 each per buffer)
#pragma unroll
    for (int i = 0; i < 16; i++) {
        int t16 = tid + i * 256;
        int k = t16 >> 5, c4 = (t16 & 31) << 2;
        cp_async16(w1s + (uint32_t)(k * DD + c4) * 4, W1 + k * HH + c4);
    }
    cp_commit();
#pragma unroll
    for (int i = 0; i < 16; i++) {
        int t16 = tid + i * 256;
        int k = t16 >> 5, c4 = (t16 & 31) << 2;
        cp_async16(w2s + (uint32_t)(k * DD + c4) * 4, W2 + k * DD + c4);
    }
    cp_commit();

    // load h rows (doubles as residual): 2 float4 per thread
#pragma unroll
    for (int i = 0; i < 2; i++) {
        int idx4 = (tid + i * 256) * 4;
        *reinterpret_cast<float4*>(&hs[idx4 >> 7][idx4 & 127]) =
            *reinterpret_cast<const float4*>(&g_h[row0 * DD + idx4]);
    }

    float acc2[8][2];
#pragma unroll
    for (int r = 0; r < 8; r++) { acc2[r][0] = 0.f; acc2[r][1] = 0.f; }

    for (int ci = 0; ci < 4; ci++) {
        const int c0 = ci * 128;
        const float* W1b = W1c + (ci & 1) * 16384;

        cp_wait1();          // W1(ci) landed
        __syncthreads();     // + hs / Usp / buffer hazards

        // ---- ff1 partial: k in [kb, kb+64), thread = 8 rows x 2 cols ----
        float acc1[8][2];
#pragma unroll
        for (int r = 0; r < 8; r++) { acc1[r][0] = 0.f; acc1[r][1] = 0.f; }
#pragma unroll 2
        for (int k0 = kb; k0 < kb + 64; k0 += 4) {
            float a[8][4];
#pragma unroll
            for (int r = 0; r < 8; r++)
                *reinterpret_cast<float4*>(a[r]) =
                    *reinterpret_cast<const float4*>(&hs[rg8 + r][k0]);
#pragma unroll
            for (int kk = 0; kk < 4; kk++) {
                float2 w = *reinterpret_cast<const float2*>(&W1b[(k0 + kk) * DD + c2]);
#pragma unroll
                for (int r = 0; r < 8; r++) {
                    acc1[r][0] = fmaf(a[r][kk], w.x, acc1[r][0]);
                    acc1[r][1] = fmaf(a[r][kk], w.y, acc1[r][1]);
                }
            }
        }
        // publish raw partials
        {
            float (*Up)[DD] = kg ? Usp1 : Us;
#pragma unroll
            for (int r = 0; r < 8; r++) {
                float2 u;
                u.x = acc1[r][0];
                u.y = acc1[r][1];
                *reinterpret_cast<float2*>(&Up[rg8 + r][c2]) = u;
            }
        }
        __syncthreads();

        // ---- combine: Us = relu(Usp0 + Usp1 + b1), 2048 floats ----
#pragma unroll
        for (int i = 0; i < 2; i++) {
            int idx4 = (tid + i * 256) * 4;
            int r = idx4 >> 7, cc = idx4 & 127;
            float4 ua = *reinterpret_cast<const float4*>(&Us[r][cc]);
            float4 ub = *reinterpret_cast<const float4*>(&Usp1[r][cc]);
            float4 bb = *reinterpret_cast<const float4*>(&b1[c0 + cc]);
            float4 u;
            u.x = fmaxf(ua.x + ub.x + bb.x, 0.0f);
            u.y = fmaxf(ua.y + ub.y + bb.y, 0.0f);
            u.z = fmaxf(ua.z + ub.z + bb.z, 0.0f);
            u.w = fmaxf(ua.w + ub.w + bb.w, 0.0f);
            *reinterpret_cast<float4*>(&Us[r][cc]) = u;
        }

        // prefetch W1(ci+1) into the other buffer (overlaps ff2)
        if (ci < 3) {
            uint32_t dst = w1s + (uint32_t)(((ci + 1) & 1) * 16384) * 4;
            const float* src = W1 + c0 + 128;
#pragma unroll
            for (int i = 0; i < 16; i++) {
                int t16 = tid + i * 256;
                int k = t16 >> 5, c4 = (t16 & 31) << 2;
                cp_async16(dst + (uint32_t)(k * DD + c4) * 4, src + k * HH + c4);
            }
            cp_commit();
        }

        if (ci < 3) cp_wait1(); else cp_wait0();   // W2(ci) landed
        __syncthreads();                            // + Us final visible

        // ---- ff2 partial: acc2 += Us @ W2c over k in [kb, kb+64) ----
#pragma unroll 2
        for (int k0 = kb; k0 < kb + 64; k0 += 4) {
            float a[8][4];
#pragma unroll
            for (int r = 0; r < 8; r++)
                *reinterpret_cast<float4*>(a[r]) =
                    *reinterpret_cast<const float4*>(&Us[rg8 + r][k0]);
#pragma unroll
            for (int kk = 0; kk < 4; kk++) {
                float2 w = *reinterpret_cast<const float2*>(&W2c[k0 + kk][c2]);
#pragma unroll
                for (int r = 0; r < 8; r++) {
                    acc2[r][0] = fmaf(a[r][kk], w.x, acc2[r][0]);
                    acc2[r][1] = fmaf(a[r][kk], w.y, acc2[r][1]);
                }
            }
        }
        __syncthreads();    // W2c + Us fully consumed

        // prefetch W2(ci+1) (overlaps next ff1)
        if (ci < 3) {
            const float* src = W2 + (c0 + 128) * DD;
#pragma unroll
            for (int i = 0; i < 16; i++) {
                int t16 = tid + i * 256;
                int k = t16 >> 5, c4 = (t16 & 31) << 2;
                cp_async16(w2s + (uint32_t)(k * DD + c4) * 4, src + k * DD + c4);
            }
            cp_commit();
        }
    }

    // ---- epilogue: combine kg partials, +b2 +residual, LN (kg0 only) ----
    if (kg == 1) {
#pragma unroll
        for (int r = 0; r < 8; r++) {
            float2 u;
            u.x = acc2[r][0];
            u.y = acc2[r][1];
            *reinterpret_cast<float2*>(&Usp1[rg8 + r][c2]) = u;
        }
    }
    __syncthreads();

    if (kg == 0) {
        float v[8][2], s[8], q[8];
        float b20 = b2[c2], b21 = b2[c2 + 1];
#pragma unroll
        for (int r = 0; r < 8; r++) {
            v[r][0] = acc2[r][0] + Usp1[rg8 + r][c2] + b20 + hs[rg8 + r][c2];
            v[r][1] = acc2[r][1] + Usp1[rg8 + r][c2 + 1] + b21 + hs[rg8 + r][c2 + 1];
            s[r] = v[r][0] + v[r][1];
            q[r] = v[r][0] * v[r][0] + v[r][1] * v[r][1];
        }
#pragma unroll
        for (int o = 16; o > 0; o >>= 1)
#pragma unroll
            for (int r = 0; r < 8; r++) {
                s[r] += __shfl_xor_sync(0xffffffffu, s[r], o);
                q[r] += __shfl_xor_sync(0xffffffffu, q[r], o);
            }
        if (lane == 0)
#pragma unroll
            for (int r = 0; r < 8; r++) { lnS[cg][rg8 + r] = s[r]; lnQ[cg][rg8 + r] = q[r]; }
        bar_sync(1, 128);     // kg0's 4 warps
        float g0 = gf[c2], g1 = gf[c2 + 1], e0 = bgf[c2], e1 = bgf[c2 + 1];
#pragma unroll
        for (int r = 0; r < 8; r++) {
            float S = lnS[0][rg8 + r] + lnS[1][rg8 + r];
            float Q = lnQ[0][rg8 + r] + lnQ[1][rg8 + r];
            float mean = S * (1.0f / DD);
            float rstd = rsqrtf(Q * (1.0f / DD) - mean * mean + LN_EPS);
            float2 o;
            o.x = (v[r][0] - mean) * rstd * g0 + e0;
            o.y = (v[r][1] - mean) * rstd * g1 + e1;
            int row = row0 + rg8 + r;
            if (FINAL) *reinterpret_cast<float2*>(&out[row * DD + c2]) = o;
            else       *reinterpret_cast<float2*>(&g_h[row * DD + c2]) = o;
        }
    }
}

extern "C" void kernel_launch(void* const* d_in, const int* in_sizes, int n_in,
                              void* d_out, int out_size) {
    const float* x   = (const float*)d_in[0];   // (8,256,2)
    const float* We  = (const float*)d_in[1];   // (2,128)
    const float* be  = (const float*)d_in[2];
    const float* ge  = (const float*)d_in[3];
    const float* bge = (const float*)d_in[4];
    const float* Wp  = (const float*)d_in[5];   // (2,256,128)
    const float* bp  = (const float*)d_in[6];
    const float* gp  = (const float*)d_in[7];
    const float* bgp = (const float*)d_in[8];
    const float* W1  = (const float*)d_in[9];   // (2,128,512)
    const float* b1  = (const float*)d_in[10];
    const float* W2  = (const float*)d_in[11];  // (2,512,128)
    const float* b2  = (const float*)d_in[12];
    const float* gf  = (const float*)d_in[13];
    const float* bgf = (const float*)d_in[14];
    float* out = (float*)d_out;                 // (8,256,128) fp32

    cudaFuncSetAttribute(pool_kernel,
                         cudaFuncAttributeMaxDynamicSharedMemorySize, POOL_SMEM);
    cudaFuncSetAttribute(ff_fused_kernel<false>,
                         cudaFuncAttributeMaxDynamicSharedMemorySize, FF_SMEM);
    cudaFuncSetAttribute(ff_fused_kernel<true>,
                         cudaFuncAttributeMaxDynamicSharedMemorySize, FF_SMEM);

    embed_ln_kernel<<<T_TOK / 16, 512>>>(x, We, be, ge, bge);

    for (int i = 0; i < 2; i++) {
        stats_kernel<<<NB * 8, 128>>>();

        pool_kernel<<<T_TOK / 16, 512, POOL_SMEM>>>(
            Wp + i * 2 * DD * DD, bp + i * DD, gp + i * DD, bgp + i * DD);

        if (i == 1)
            ff_fused_kernel<true><<<T_TOK / 16, 256, FF_SMEM>>>(
                W1 + i * DD * HH, b1 + i * HH, W2 + i * HH * DD, b2 + i * DD,
                gf + i * DD, bgf + i * DD, out);
        else
            ff_fused_kernel<false><<<T_TOK / 16, 256, FF_SMEM>>>(
                W1 + i * DD * HH, b1 + i * HH, W2 + i * HH * DD, b2 + i * DD,
                gf + i * DD, bgf + i * DD, nullptr);
    }
}

// round 17
// speedup vs baseline: 1.1147x; 1.0214x over previous
#include <cuda_runtime.h>
#include <cstdint>

// PermutationInvariantNet: B=8, N=256, IN_DIM=2, D=128, H=512, L=2
// Tokens T = B*N = 2048. fp32.
// 5 launches: embed, 2x { stats(64 blocks), layer(pool+ff fused) }.
// layer kernel: pool phase (2kg x rpt=8 core, Wp in W1c buffers, stats merge
// + pooled-A synth overlap the cp.async) -> new h stays in smem hs ->
// ff phase (R14/R16-proven rpt=8 k-split core). Pooled h never hits gmem.

#define T_TOK 2048
#define NB 8
#define NN 256
#define DD 128
#define HH 512
#define LN_EPS 1e-5f
#define NEG_INF -3.402823466e38f

__device__ __align__(16) float g_h[T_TOK * DD];   // hidden state (1 MB)
__device__ float g_sm1[NB * 8 * DD];              // slice max1 (8 slices/batch)
__device__ float g_sm2[NB * 8 * DD];              // slice max2
__device__ int   g_si1[NB * 8 * DD];              // slice argmax

// -------- cp.async helpers --------
__device__ __forceinline__ void cp_async16(uint32_t dst, const void* src) {
    asm volatile("cp.async.cg.shared.global [%0], [%1], 16;" :: "r"(dst), "l"(src));
}
__device__ __forceinline__ void cp_commit() { asm volatile("cp.async.commit_group;"); }
__device__ __forceinline__ void cp_wait1()  { asm volatile("cp.async.wait_group 1;"); }
__device__ __forceinline__ void cp_wait0()  { asm volatile("cp.async.wait_group 0;"); }
__device__ __forceinline__ void bar_sync(int id, int cnt) {
    asm volatile("bar.sync %0, %1;" :: "r"(id), "r"(cnt) : "memory");
}

// ===================== embed + LN (warp per token) =====================
__global__ void __launch_bounds__(512)
embed_ln_kernel(const float* __restrict__ x, const float* __restrict__ We,
                const float* __restrict__ be, const float* __restrict__ ge,
                const float* __restrict__ bge) {
    int wid = threadIdx.x >> 5, lane = threadIdx.x & 31;
    int t = blockIdx.x * 16 + wid;
    float2 xx = *reinterpret_cast<const float2*>(x + t * 2);
    float y[4], s = 0.0f, q = 0.0f;
#pragma unroll
    for (int j = 0; j < 4; j++) {
        int d = lane + j * 32;
        y[j] = fmaf(xx.x, We[d], fmaf(xx.y, We[DD + d], be[d]));
        s += y[j];
        q += y[j] * y[j];
    }
#pragma unroll
    for (int o = 16; o > 0; o >>= 1) {
        s += __shfl_xor_sync(0xffffffffu, s, o);
        q += __shfl_xor_sync(0xffffffffu, q, o);
    }
    float mean = s * (1.0f / DD);
    float rstd = rsqrtf(q * (1.0f / DD) - mean * mean + LN_EPS);
#pragma unroll
    for (int j = 0; j < 4; j++) {
        int d = lane + j * 32;
        g_h[t * DD + d] = (y[j] - mean) * rstd * ge[d] + bge[d];
    }
}

// ===================== distributed stats: 64 blocks of (batch, slice) ======
__global__ void __launch_bounds__(128)
stats_kernel() {
    int blk = blockIdx.x;
    int b = blk >> 3, sl = blk & 7;
    int d = threadIdx.x;
    const float* hb = g_h + b * NN * DD;

    float m1 = NEG_INF, m2 = NEG_INF;
    int i1 = 0;
    int n0 = sl * 32;
#pragma unroll 8
    for (int n = n0; n < n0 + 32; n++) {
        float v = hb[n * DD + d];
        if (v > m1) { m2 = m1; m1 = v; i1 = n; }
        else if (v > m2) { m2 = v; }
    }
    int idx = (b * 8 + sl) * DD + d;
    g_sm1[idx] = m1;
    g_sm2[idx] = m2;
    g_si1[idx] = i1;
}

// ===================== fused layer: pool + ff =====================
// h' = LN(h + relu(LN(h + [h,loo(h)]@Wp + bp)@W1 + b1)@W2 + b2)  [per layer]
// 256 thr = 8 warps = 2rg x 2cg x 2kg, thread = 8 rows x 2 cols everywhere.
// Pool: kg0 contracts h-part (Wp rows 0..127, A=hs), kg1 pooled part
// (Wp rows 128..255 in W1c buf1, A=Us synthesized from merged stats).
// New h written to hs only. ff: R14 core (W1 double-buffered, k-split kgs).
// smem floats: hs 0 [16][128] | W1c 2048 [2][128][128] | W2c 34816 [128][128]
//   | Us 51200 [16][128] | Usp1 53248 [16][128] | lnS 55296 [2][16]
//   | lnQ 55328 | m1f 55360 [128] | m2f 55488 [128] | i1f 55616 [128] (int)
#define LAYER_SMEM (55744 * 4)
template <bool FINAL>
__global__ void __launch_bounds__(256, 1)
layer_kernel(const float* __restrict__ Wp, const float* __restrict__ bp,
             const float* __restrict__ gp, const float* __restrict__ bgp,
             const float* __restrict__ W1, const float* __restrict__ b1,
             const float* __restrict__ W2, const float* __restrict__ b2,
             const float* __restrict__ gf, const float* __restrict__ bgf,
             float* __restrict__ out) {
    extern __shared__ float sm[];
    float (*hs)[DD]   = reinterpret_cast<float (*)[DD]>(sm);
    float* W1c        = sm + 2048;
    float (*W2c)[DD]  = reinterpret_cast<float (*)[DD]>(sm + 34816);
    float (*Us)[DD]   = reinterpret_cast<float (*)[DD]>(sm + 51200);
    float (*Usp1)[DD] = reinterpret_cast<float (*)[DD]>(sm + 53248);
    float (*lnS)[16]  = reinterpret_cast<float (*)[16]>(sm + 55296);
    float (*lnQ)[16]  = reinterpret_cast<float (*)[16]>(sm + 55328);
    float* m1f        = sm + 55360;
    float* m2f        = sm + 55488;
    int*   i1f        = reinterpret_cast<int*>(sm + 55616);

    const int tid = threadIdx.x;
    const int lane = tid & 31, wid = tid >> 5;
    const int kg = wid >> 2;            // warps 0-3 kg0, 4-7 kg1
    const int rg = (wid >> 1) & 1;
    const int cg = wid & 1;
    const int rg8 = rg * 8;
    const int c2 = cg * 64 + lane * 2;
    const int kb = kg * 64;             // ff k-offset within each 128 range
    const int row0 = blockIdx.x * 16;
    const int b = row0 >> 8;
    const int nbase = row0 & 255;

    const uint32_t w1s = (uint32_t)__cvta_generic_to_shared(W1c);
    const uint32_t w2s = (uint32_t)__cvta_generic_to_shared(&W2c[0][0]);

    // ============ POOL PHASE ============
    // per-thread cp groups: [Wp-half, W2c0, (later) W1c0, prefetches...]
    if (kg == 0) {
        // Wp top 128 rows -> W1c buf0 (128 threads x 32 float4)
#pragma unroll
        for (int i = 0; i < 32; i++) {
            int t16 = tid + i * 128;            // 0..4095
            int k = t16 >> 5, c4 = (t16 & 31) << 2;
            cp_async16(w1s + (uint32_t)(k * DD + c4) * 4, Wp + k * DD + c4);
        }
        cp_commit();
        // load hs (h rows; pool A + pool residual): 4 float4 each
#pragma unroll
        for (int i = 0; i < 4; i++) {
            int idx4 = (tid + i * 128) * 4;
            *reinterpret_cast<float4*>(&hs[idx4 >> 7][idx4 & 127]) =
                *reinterpret_cast<const float4*>(&g_h[row0 * DD + idx4]);
        }
    } else {
        const int tk = tid - 128;               // 0..127
        // Wp bottom 128 rows -> W1c buf1
        const float* Wbot = Wp + DD * DD;
#pragma unroll
        for (int i = 0; i < 32; i++) {
            int t16 = tk + i * 128;
            int k = t16 >> 5, c4 = (t16 & 31) << 2;
            cp_async16(w1s + (uint32_t)(16384 + k * DD + c4) * 4,
                       Wbot + k * DD + c4);
        }
        cp_commit();
        // merge 8 slice-stats (feature d = tk; ascending slice order keeps
        // first-argmax tie semantics); overlaps the cp.async
        {
            int base = b * 8 * DD + tk;
            float m1 = g_sm1[base], m2 = g_sm2[base];
            int i1 = g_si1[base];
#pragma unroll
            for (int j = 1; j < 8; j++) {
                float a1 = g_sm1[base + j * DD], a2 = g_sm2[base + j * DD];
                int ai = g_si1[base + j * DD];
                if (a1 > m1) { m2 = fmaxf(m1, a2); m1 = a1; i1 = ai; }
                else         { m2 = fmaxf(m2, a1); }
            }
            m1f[tk] = m1; m2f[tk] = m2; i1f[tk] = i1;
        }
        bar_sync(2, 128);   // merged stats visible within kg1
        // synthesize pooled A-tile into Us: 16 elems per thread
#pragma unroll
        for (int i = 0; i < 16; i++) {
            int idx = tk + i * 128;             // 0..2047
            int r = idx >> 7, kcol = idx & 127;
            Us[r][kcol] = (nbase + r == i1f[kcol]) ? m2f[kcol] : m1f[kcol];
        }
    }
    // W2 chunk0 prefetch (all threads) — W2c idle during pool
#pragma unroll
    for (int i = 0; i < 16; i++) {
        int t16 = tid + i * 256;
        int k = t16 >> 5, c4 = (t16 & 31) << 2;
        cp_async16(w2s + (uint32_t)(k * DD + c4) * 4, W2 + k * DD + c4);
    }
    cp_commit();

    cp_wait1();          // own Wp half landed (W2c0 still flying)
    __syncthreads();     // hs + Us + all Wp loads visible

    // ---- pool GEMM: kg0 = h-part (buf0), kg1 = pooled part (buf1) ----
    float acc[8][2];
#pragma unroll
    for (int r = 0; r < 8; r++) { acc[r][0] = 0.f; acc[r][1] = 0.f; }
    {
        const float* Wpb = W1c + kg * 16384;
        const float (*Ap)[DD] = kg ? Us : hs;
#pragma unroll 2
        for (int k0 = 0; k0 < 128; k0 += 4) {
            float a[8][4];
#pragma unroll
            for (int r = 0; r < 8; r++)
                *reinterpret_cast<float4*>(a[r]) =
                    *reinterpret_cast<const float4*>(&Ap[rg8 + r][k0]);
#pragma unroll
            for (int kk = 0; kk < 4; kk++) {
                float2 w = *reinterpret_cast<const float2*>(&Wpb[(k0 + kk) * DD + c2]);
#pragma unroll
                for (int r = 0; r < 8; r++) {
                    acc[r][0] = fmaf(a[r][kk], w.x, acc[r][0]);
                    acc[r][1] = fmaf(a[r][kk], w.y, acc[r][1]);
                }
            }
        }
    }
    if (kg == 1) {
#pragma unroll
        for (int r = 0; r < 8; r++) {
            float2 u; u.x = acc[r][0]; u.y = acc[r][1];
            *reinterpret_cast<float2*>(&Usp1[rg8 + r][c2]) = u;
        }
    }
    __syncthreads();     // partials visible; W1c buffers fully consumed

    // issue W1 chunk0 -> buf0 (overlaps pool epilogue)
#pragma unroll
    for (int i = 0; i < 16; i++) {
        int t16 = tid + i * 256;
        int k = t16 >> 5, c4 = (t16 & 31) << 2;
        cp_async16(w1s + (uint32_t)(k * DD + c4) * 4, W1 + k * HH + c4);
    }
    cp_commit();

    // ---- pool epilogue (kg0): combine + bp + residual + LN -> hs ----
    if (kg == 0) {
        float v[8][2], s[8], q[8];
        float bp0 = bp[c2], bp1 = bp[c2 + 1];
#pragma unroll
        for (int r = 0; r < 8; r++) {
            v[r][0] = acc[r][0] + Usp1[rg8 + r][c2] + bp0 + hs[rg8 + r][c2];
            v[r][1] = acc[r][1] + Usp1[rg8 + r][c2 + 1] + bp1 + hs[rg8 + r][c2 + 1];
            s[r] = v[r][0] + v[r][1];
            q[r] = v[r][0] * v[r][0] + v[r][1] * v[r][1];
        }
#pragma unroll
        for (int o = 16; o > 0; o >>= 1)
#pragma unroll
            for (int r = 0; r < 8; r++) {
                s[r] += __shfl_xor_sync(0xffffffffu, s[r], o);
                q[r] += __shfl_xor_sync(0xffffffffu, q[r], o);
            }
        if (lane == 0)
#pragma unroll
            for (int r = 0; r < 8; r++) { lnS[cg][rg8 + r] = s[r]; lnQ[cg][rg8 + r] = q[r]; }
        bar_sync(1, 128);
        float g0 = gp[c2], g1 = gp[c2 + 1], e0 = bgp[c2], e1 = bgp[c2 + 1];
#pragma unroll
        for (int r = 0; r < 8; r++) {
            float S = lnS[0][rg8 + r] + lnS[1][rg8 + r];
            float Q = lnQ[0][rg8 + r] + lnQ[1][rg8 + r];
            float mean = S * (1.0f / DD);
            float rstd = rsqrtf(Q * (1.0f / DD) - mean * mean + LN_EPS);
            float2 o;
            o.x = (v[r][0] - mean) * rstd * g0 + e0;
            o.y = (v[r][1] - mean) * rstd * g1 + e1;
            *reinterpret_cast<float2*>(&hs[rg8 + r][c2]) = o;   // new h, smem only
        }
    }

    // ============ FF PHASE (R14/R16 core) ============
    float acc2[8][2];
#pragma unroll
    for (int r = 0; r < 8; r++) { acc2[r][0] = 0.f; acc2[r][1] = 0.f; }

    for (int ci = 0; ci < 4; ci++) {
        const int c0 = ci * 128;
        const float* W1b = W1c + (ci & 1) * 16384;

        if (ci == 0) cp_wait0(); else cp_wait1();   // W1(ci) landed
        __syncthreads();     // + hs (new h) / Usp / buffer hazards

        // ---- ff1 partial: k in [kb, kb+64), thread = 8 rows x 2 cols ----
        float acc1[8][2];
#pragma unroll
        for (int r = 0; r < 8; r++) { acc1[r][0] = 0.f; acc1[r][1] = 0.f; }
#pragma unroll 2
        for (int k0 = kb; k0 < kb + 64; k0 += 4) {
            float a[8][4];
#pragma unroll
            for (int r = 0; r < 8; r++)
                *reinterpret_cast<float4*>(a[r]) =
                    *reinterpret_cast<const float4*>(&hs[rg8 + r][k0]);
#pragma unroll
            for (int kk = 0; kk < 4; kk++) {
                float2 w = *reinterpret_cast<const float2*>(&W1b[(k0 + kk) * DD + c2]);
#pragma unroll
                for (int r = 0; r < 8; r++) {
                    acc1[r][0] = fmaf(a[r][kk], w.x, acc1[r][0]);
                    acc1[r][1] = fmaf(a[r][kk], w.y, acc1[r][1]);
                }
            }
        }
        // publish raw partials
        {
            float (*Up)[DD] = kg ? Usp1 : Us;
#pragma unroll
            for (int r = 0; r < 8; r++) {
                float2 u; u.x = acc1[r][0]; u.y = acc1[r][1];
                *reinterpret_cast<float2*>(&Up[rg8 + r][c2]) = u;
            }
        }
        __syncthreads();

        // ---- combine: Us = relu(Usp0 + Usp1 + b1) ----
#pragma unroll
        for (int i = 0; i < 2; i++) {
            int idx4 = (tid + i * 256) * 4;
            int r = idx4 >> 7, cc = idx4 & 127;
            float4 ua = *reinterpret_cast<const float4*>(&Us[r][cc]);
            float4 ub = *reinterpret_cast<const float4*>(&Usp1[r][cc]);
            float4 bb = *reinterpret_cast<const float4*>(&b1[c0 + cc]);
            float4 u;
            u.x = fmaxf(ua.x + ub.x + bb.x, 0.0f);
            u.y = fmaxf(ua.y + ub.y + bb.y, 0.0f);
            u.z = fmaxf(ua.z + ub.z + bb.z, 0.0f);
            u.w = fmaxf(ua.w + ub.w + bb.w, 0.0f);
            *reinterpret_cast<float4*>(&Us[r][cc]) = u;
        }

        // prefetch W1(ci+1) (overlaps ff2)
        if (ci < 3) {
            uint32_t dst = w1s + (uint32_t)(((ci + 1) & 1) * 16384) * 4;
            const float* src = W1 + c0 + 128;
#pragma unroll
            for (int i = 0; i < 16; i++) {
                int t16 = tid + i * 256;
                int k = t16 >> 5, c4 = (t16 & 31) << 2;
                cp_async16(dst + (uint32_t)(k * DD + c4) * 4, src + k * HH + c4);
            }
            cp_commit();
        }

        if (ci < 3) cp_wait1(); else cp_wait0();   // W2(ci) landed
        __syncthreads();                            // + Us final visible

        // ---- ff2 partial: acc2 += Us @ W2c over k in [kb, kb+64) ----
#pragma unroll 2
        for (int k0 = kb; k0 < kb + 64; k0 += 4) {
            float a[8][4];
#pragma unroll
            for (int r = 0; r < 8; r++)
                *reinterpret_cast<float4*>(a[r]) =
                    *reinterpret_cast<const float4*>(&Us[rg8 + r][k0]);
#pragma unroll
            for (int kk = 0; kk < 4; kk++) {
                float2 w = *reinterpret_cast<const float2*>(&W2c[k0 + kk][c2]);
#pragma unroll
                for (int r = 0; r < 8; r++) {
                    acc2[r][0] = fmaf(a[r][kk], w.x, acc2[r][0]);
                    acc2[r][1] = fmaf(a[r][kk], w.y, acc2[r][1]);
                }
            }
        }
        __syncthreads();    // W2c + Us fully consumed

        // prefetch W2(ci+1) (overlaps next ff1)
        if (ci < 3) {
            const float* src = W2 + (c0 + 128) * DD;
#pragma unroll
            for (int i = 0; i < 16; i++) {
                int t16 = tid + i * 256;
                int k = t16 >> 5, c4 = (t16 & 31) << 2;
                cp_async16(w2s + (uint32_t)(k * DD + c4) * 4, src + k * DD + c4);
            }
            cp_commit();
        }
    }

    // ---- ff epilogue: combine kg partials, +b2 +residual, LN (kg0) ----
    if (kg == 1) {
#pragma unroll
        for (int r = 0; r < 8; r++) {
            float2 u; u.x = acc2[r][0]; u.y = acc2[r][1];
            *reinterpret_cast<float2*>(&Usp1[rg8 + r][c2]) = u;
        }
    }
    __syncthreads();

    if (kg == 0) {
        float v[8][2], s[8], q[8];
        float b20 = b2[c2], b21 = b2[c2 + 1];
#pragma unroll
        for (int r = 0; r < 8; r++) {
            v[r][0] = acc2[r][0] + Usp1[rg8 + r][c2] + b20 + hs[rg8 + r][c2];
            v[r][1] = acc2[r][1] + Usp1[rg8 + r][c2 + 1] + b21 + hs[rg8 + r][c2 + 1];
            s[r] = v[r][0] + v[r][1];
            q[r] = v[r][0] * v[r][0] + v[r][1] * v[r][1];
        }
#pragma unroll
        for (int o = 16; o > 0; o >>= 1)
#pragma unroll
            for (int r = 0; r < 8; r++) {
                s[r] += __shfl_xor_sync(0xffffffffu, s[r], o);
                q[r] += __shfl_xor_sync(0xffffffffu, q[r], o);
            }
        if (lane == 0)
#pragma unroll
            for (int r = 0; r < 8; r++) { lnS[cg][rg8 + r] = s[r]; lnQ[cg][rg8 + r] = q[r]; }
        bar_sync(1, 128);
        float g0 = gf[c2], g1 = gf[c2 + 1], e0 = bgf[c2], e1 = bgf[c2 + 1];
#pragma unroll
        for (int r = 0; r < 8; r++) {
            float S = lnS[0][rg8 + r] + lnS[1][rg8 + r];
            float Q = lnQ[0][rg8 + r] + lnQ[1][rg8 + r];
            float mean = S * (1.0f / DD);
            float rstd = rsqrtf(Q * (1.0f / DD) - mean * mean + LN_EPS);
            float2 o;
            o.x = (v[r][0] - mean) * rstd * g0 + e0;
            o.y = (v[r][1] - mean) * rstd * g1 + e1;
            int row = row0 + rg8 + r;
            if (FINAL) *reinterpret_cast<float2*>(&out[row * DD + c2]) = o;
            else       *reinterpret_cast<float2*>(&g_h[row * DD + c2]) = o;
        }
    }
}

extern "C" void kernel_launch(void* const* d_in, const int* in_sizes, int n_in,
                              void* d_out, int out_size) {
    const float* x   = (const float*)d_in[0];   // (8,256,2)
    const float* We  = (const float*)d_in[1];   // (2,128)
    const float* be  = (const float*)d_in[2];
    const float* ge  = (const float*)d_in[3];
    const float* bge = (const float*)d_in[4];
    const float* Wp  = (const float*)d_in[5];   // (2,256,128)
    const float* bp  = (const float*)d_in[6];
    const float* gp  = (const float*)d_in[7];
    const float* bgp = (const float*)d_in[8];
    const float* W1  = (const float*)d_in[9];   // (2,128,512)
    const float* b1  = (const float*)d_in[10];
    const float* W2  = (const float*)d_in[11];  // (2,512,128)
    const float* b2  = (const float*)d_in[12];
    const float* gf  = (const float*)d_in[13];
    const float* bgf = (const float*)d_in[14];
    float* out = (float*)d_out;                 // (8,256,128) fp32

    cudaFuncSetAttribute(layer_kernel<false>,
                         cudaFuncAttributeMaxDynamicSharedMemorySize, LAYER_SMEM);
    cudaFuncSetAttribute(layer_kernel<true>,
                         cudaFuncAttributeMaxDynamicSharedMemorySize, LAYER_SMEM);

    embed_ln_kernel<<<T_TOK / 16, 512>>>(x, We, be, ge, bge);

    for (int i = 0; i < 2; i++) {
        stats_kernel<<<NB * 8, 128>>>();

        if (i == 1)
            layer_kernel<true><<<T_TOK / 16, 256, LAYER_SMEM>>>(
                Wp + i * 2 * DD * DD, bp + i * DD, gp + i * DD, bgp + i * DD,
                W1 + i * DD * HH, b1 + i * HH, W2 + i * HH * DD, b2 + i * DD,
                gf + i * DD, bgf + i * DD, out);
        else
            layer_kernel<false><<<T_TOK / 16, 256, LAYER_SMEM>>>(
                Wp + i * 2 * DD * DD, bp + i * DD, gp + i * DD, bgp + i * DD,
                W1 + i * DD * HH, b1 + i * HH, W2 + i * HH * DD, b2 + i * DD,
                gf + i * DD, bgf + i * DD, nullptr);
    }
}